// round 9
// baseline (speedup 1.0000x reference)
#include <cuda_runtime.h>
#include <math.h>

#define N_NODES  50000
#define N_EDGES  800000
#define NODE_DIM 64
#define EDGE_DIM 32
#define HID      128
#define EPB      8
#define TPB      256
#define WPB      (TPB / 32)
#define NB       4096          // table bins over d in [0,15]
#define TB_BINS  8

typedef unsigned long long ull;

// Per-node precomputed rows [ns(128) | nd(128) | cs(128) | cd(128)]
__device__ float g_A[(size_t)N_NODES * 512];
// Folded edge-path weights (used only to build the table)
__device__ float g_Mn[32 * 128];
__device__ float g_Mc[32 * 128];
__device__ float g_bn[128];
__device__ float g_bc[128];
// Interp table: row i = [F(d_i)+bn (128) | G(d_i)+bc (128)], d_i = i*15/NB
__device__ float g_T[(size_t)(NB + 1) * 256];
// Rearranged Wn2: WA[i*32+l] = Wn2[4i..4i+3][2l], WB same for 2l+1
__device__ float4 g_WA[1024];
__device__ float4 g_WB[1024];

union F4 { float4 f; ulonglong2 u; };
union F2 { float2 f; ull u; };

__device__ __forceinline__ ull pk2(float x, float y) {
    ull r; asm("mov.b64 %0,{%1,%2};" : "=l"(r) : "f"(x), "f"(y)); return r;
}
__device__ __forceinline__ void upk2(ull v, float& x, float& y) {
    asm("mov.b64 {%0,%1},%2;" : "=f"(x), "=f"(y) : "l"(v));
}
__device__ __forceinline__ ull ffma2(ull a, ull b, ull c) {
    ull d; asm("fma.rn.f32x2 %0,%1,%2,%3;" : "=l"(d) : "l"(a), "l"(b), "l"(c)); return d;
}
__device__ __forceinline__ ull fadd2(ull a, ull b) {
    ull d; asm("add.rn.f32x2 %0,%1,%2;" : "=l"(d) : "l"(a), "l"(b)); return d;
}
// silu via MUFU tanh: silu(z) = hz + hz*tanh(hz), hz = z/2
__device__ __forceinline__ float silu1(float z) {
    float hz = 0.5f * z;
    float th;
    asm("tanh.approx.f32 %0, %1;" : "=f"(th) : "f"(hz));
    return fmaf(hz, th, hz);
}

// ---------------------------------------------------------------------------
// K0: fold edge-path weights + rearrange Wn2
// ---------------------------------------------------------------------------
__global__ void k_fold(const float* __restrict__ We2, const float* __restrict__ be2,
                       const float* __restrict__ Wn1, const float* __restrict__ bn1,
                       const float* __restrict__ Wc1, const float* __restrict__ bc1,
                       const float* __restrict__ Wn2) {
    int j = threadIdx.x;  // 0..127
    float bn = bn1[j], bc = bc1[j];
    for (int b = 0; b < 32; b++) {
        bn += be2[b] * Wn1[(128 + b) * 128 + j];
        bc += be2[b] * Wc1[(128 + b) * 128 + j];
    }
    g_bn[j] = bn;
    g_bc[j] = bc;
    for (int a = 0; a < 32; a++) {
        float sn = 0.f, sc = 0.f;
        for (int b = 0; b < 32; b++) {
            float w = We2[a * 32 + b];
            sn += w * Wn1[(128 + b) * 128 + j];
            sc += w * Wc1[(128 + b) * 128 + j];
        }
        g_Mn[a * 128 + j] = sn;
        g_Mc[a * 128 + j] = sc;
    }
    for (int idx = j; idx < 1024; idx += 128) {
        int i = idx >> 5, l = idx & 31;
        g_WA[idx] = make_float4(Wn2[(4 * i + 0) * 64 + 2 * l], Wn2[(4 * i + 1) * 64 + 2 * l],
                                Wn2[(4 * i + 2) * 64 + 2 * l], Wn2[(4 * i + 3) * 64 + 2 * l]);
        g_WB[idx] = make_float4(Wn2[(4 * i + 0) * 64 + 2 * l + 1], Wn2[(4 * i + 1) * 64 + 2 * l + 1],
                                Wn2[(4 * i + 2) * 64 + 2 * l + 1], Wn2[(4 * i + 3) * 64 + 2 * l + 1]);
    }
}

// ---------------------------------------------------------------------------
// K0b: build edge-path interp table. TB_BINS bins per block, smem-staged M.
// ---------------------------------------------------------------------------
__global__ void k_tab(const float* __restrict__ We1, const float* __restrict__ be1) {
    __shared__ float M_sh[8192];   // Mn(4096) | Mc(4096)
    __shared__ float b_sh[256];    // bn(128) | bc(128)
    __shared__ float t_sh[32];
    int j = threadIdx.x;           // 0..255
    for (int i = j; i < 4096; i += 256) {
        M_sh[i]        = g_Mn[i];
        M_sh[4096 + i] = g_Mc[i];
    }
    if (j < 128) {
        b_sh[j]       = g_bn[j];
        b_sh[128 + j] = g_bc[j];
    }
    __syncthreads();

    const float* M = (j < 128) ? M_sh : (M_sh + 4096);
    int jj = j & 127;
    float bb = b_sh[j];

    for (int bi = 0; bi < TB_BINS; bi++) {
        int i = blockIdx.x * TB_BINS + bi;
        if (i > NB) break;
        float d = (15.0f / NB) * i;
        if (j < 32) {
            float z = d * We1[j] + be1[j];
            t_sh[j] = z / (1.f + __expf(-z));   // exact silu for table accuracy
        }
        __syncthreads();
        float s = bb;
#pragma unroll 8
        for (int k = 0; k < 32; k++) s += t_sh[k] * M[k * 128 + jj];
        g_T[(size_t)i * 256 + j] = s;
        __syncthreads();
    }
}

// ---------------------------------------------------------------------------
// K1: per-node precompute, f32x2 math. 256 threads, NPB=32 nodes per block.
// thread j: part m = j>>6 (ns|nd|cs|cd), 2 cols c..c+1 of that part.
// ---------------------------------------------------------------------------
#define NPB 32
__global__ void k_node(const float* __restrict__ h,
                       const float* __restrict__ Wn1,
                       const float* __restrict__ Wc1) {
    __shared__ ull h2[NPB * 64];   // duplicated {h,h} pairs (16 KB)
    int node0 = blockIdx.x * NPB;
    for (int i = threadIdx.x; i < NPB * 64; i += 256) {
        int idx = node0 * 64 + i;
        float hv = (idx < N_NODES * 64) ? h[idx] : 0.f;
        h2[i] = pk2(hv, hv);
    }
    __syncthreads();
    int j = threadIdx.x;
    int m = j >> 6;               // 0..3
    int c = (j & 63) * 2;         // 0..126
    const float* W = ((m & 2) ? Wc1 : Wn1) + ((m & 1) ? 64 * 128 : 0);

    ull a0[NPB];
#pragma unroll
    for (int n = 0; n < NPB; n++) a0[n] = 0ull;
#pragma unroll 4
    for (int k = 0; k < 64; k++) {
        F2 w; w.f = *(const float2*)&W[k * 128 + c];
#pragma unroll
        for (int n = 0; n < NPB; n++)
            a0[n] = ffma2(h2[n * 64 + k], w.u, a0[n]);
    }
#pragma unroll
    for (int n = 0; n < NPB; n++) {
        int node = node0 + n;
        if (node < N_NODES) {
            F2 r; r.u = a0[n];
            *(float2*)&g_A[(size_t)node * 512 + m * 128 + c] = r.f;
        }
    }
}

// ---------------------------------------------------------------------------
// K2: initialize output with (h, x)
// ---------------------------------------------------------------------------
__global__ void k_init(const float* __restrict__ h, const float* __restrict__ x,
                       float* __restrict__ out) {
    int nh = N_NODES * NODE_DIM;
    int tot = nh + N_NODES * 3;
    for (int i = blockIdx.x * blockDim.x + threadIdx.x; i < tot; i += gridDim.x * blockDim.x)
        out[i] = (i < nh) ? h[i] : x[i - nh];
}

// ---------------------------------------------------------------------------
// K3: edge kernel. Table-lookup edge path; no k-loops, no spills.
// ---------------------------------------------------------------------------
__global__ void __launch_bounds__(TPB, 2)
k_edge(const float* __restrict__ dist,
       const int*   __restrict__ eidx,
       const float* __restrict__ x,
       const float* __restrict__ bn2,
       const float* __restrict__ Wc2,
       float* __restrict__ out) {
    extern __shared__ float sm[];
    float4* WA_sh = (float4*)sm;               // 1024 f4
    float4* WB_sh = WA_sh + 1024;              // 1024 f4
    float*  gbuf  = (float*)(WB_sh + 1024);    // WPB warps * 1024
    float*  Wc2_sh = gbuf + WPB * 1024;        // 128
    float*  bn2_sh = Wc2_sh + 128;             // 64

    for (int i = threadIdx.x; i < 1024; i += blockDim.x) {
        WA_sh[i] = g_WA[i];
        WB_sh[i] = g_WB[i];
    }
    if (threadIdx.x < 128) Wc2_sh[threadIdx.x] = Wc2[threadIdx.x];
    if (threadIdx.x < 64)  bn2_sh[threadIdx.x] = bn2[threadIdx.x];
    __syncthreads();

    const int lane = threadIdx.x & 31;
    const int wib  = threadIdx.x >> 5;
    const int gw   = blockIdx.x * WPB + wib;
    const int nw   = gridDim.x * WPB;

    F4 wc2_4; wc2_4.f = *(const float4*)&Wc2_sh[4 * lane];
    const float2 bn2_2 = *(const float2*)&bn2_sh[2 * lane];
    float* gb = gbuf + wib * 1024;
    const float4* A4 = (const float4*)g_A;
    const float4* T4 = (const float4*)g_T;     // 64 f4 per table row
    const float4* gb4 = (const float4*)gb;
    float* out_x = out + (size_t)N_NODES * 64;

    for (int base = gw * EPB; base < N_EDGES; base += nw * EPB) {
        int src[EPB], dstn[EPB];
        float cw[EPB];

        // ---- per-edge: table-interp edge path + node terms for both MLPs ----
#pragma unroll
        for (int ee = 0; ee < EPB; ee++) {
            int e = base + ee;
            float d = dist[e];
            int s  = eidx[e];
            int dd = eidx[N_EDGES + e];
            src[ee] = s; dstn[ee] = dd;

            float p = d * (NB / 15.0f);
            int i0 = (int)p;
            i0 = max(0, min(i0, NB - 1));
            float w = p - (float)i0;
            ull w2   = pk2(w, w);
            ull w1m2 = pk2(1.f - w, 1.f - w);
            const float4* t0 = T4 + (size_t)i0 * 64;
            const float4* t1 = t0 + 64;

            // node-MLP hidden: pn = A_ns[src] + A_nd[dst] + lerp(F)
            {
                F4 a;  a.f  = A4[(size_t)s  * 128 + lane];
                F4 b;  b.f  = A4[(size_t)dd * 128 + 32 + lane];
                F4 f0; f0.f = t0[lane];
                F4 f1; f1.f = t1[lane];
                ull px = fadd2(a.u.x, b.u.x);
                ull py = fadd2(a.u.y, b.u.y);
                px = ffma2(w1m2, f0.u.x, px);
                py = ffma2(w1m2, f0.u.y, py);
                px = ffma2(w2, f1.u.x, px);
                py = ffma2(w2, f1.u.y, py);
                float p0, p1, p2, p3;
                upk2(px, p0, p1);
                upk2(py, p2, p3);
                float4 gn = make_float4(silu1(p0), silu1(p1), silu1(p2), silu1(p3));
                *(float4*)&gb[ee * 128 + 4 * lane] = gn;
            }
            // coord-MLP hidden -> scalar cw
            {
                F4 c;  c.f  = A4[(size_t)s  * 128 + 64 + lane];
                F4 dv; dv.f = A4[(size_t)dd * 128 + 96 + lane];
                F4 g0; g0.f = t0[32 + lane];
                F4 g1; g1.f = t1[32 + lane];
                ull px = fadd2(c.u.x, dv.u.x);
                ull py = fadd2(c.u.y, dv.u.y);
                px = ffma2(w1m2, g0.u.x, px);
                py = ffma2(w1m2, g0.u.y, py);
                px = ffma2(w2, g1.u.x, px);
                py = ffma2(w2, g1.u.y, py);
                float p0, p1, p2, p3;
                upk2(px, p0, p1);
                upk2(py, p2, p3);
                float ss = silu1(p0) * wc2_4.f.x + silu1(p1) * wc2_4.f.y
                         + silu1(p2) * wc2_4.f.z + silu1(p3) * wc2_4.f.w;
#pragma unroll
                for (int off = 16; off > 0; off >>= 1)
                    ss += __shfl_xor_sync(0xffffffffu, ss, off);
                cw[ee] = ss;
            }
        }

        // ---- coord scatter (lanes 0..7, one edge each) ----
        if (lane < EPB) {
            float mycw = cw[0]; int ms = src[0], md = dstn[0];
#pragma unroll
            for (int ee = 1; ee < EPB; ee++)
                if (lane == ee) { mycw = cw[ee]; ms = src[ee]; md = dstn[ee]; }
            float dx = x[ms * 3 + 0] - x[md * 3 + 0];
            float dy = x[ms * 3 + 1] - x[md * 3 + 1];
            float dz = x[ms * 3 + 2] - x[md * 3 + 2];
            float len = fmaxf(sqrtf(dx * dx + dy * dy + dz * dz), 1e-8f);
            float inv = mycw / len;
            float* ox = out_x + (size_t)md * 3;
            atomicAdd(&ox[0], dx * inv);
            atomicAdd(&ox[1], dy * inv);
            atomicAdd(&ox[2], dz * inv);
        }
        __syncwarp();

        // ---- phase 2: gn(128) @ Wn2 -> 64 ----
        ull macA[EPB], macB[EPB];
#pragma unroll
        for (int ee = 0; ee < EPB; ee++) {
            macA[ee] = pk2(bn2_2.x, 0.f);
            macB[ee] = pk2(bn2_2.y, 0.f);
        }
#pragma unroll
        for (int i = 0; i < 32; i++) {
            F4 wA; wA.f = WA_sh[i * 32 + lane];
            F4 wB; wB.f = WB_sh[i * 32 + lane];
#pragma unroll
            for (int ee = 0; ee < EPB; ee++) {
                F4 g; g.f = gb4[ee * 32 + i];  // broadcast
                macA[ee] = ffma2(g.u.x, wA.u.x, macA[ee]);
                macA[ee] = ffma2(g.u.y, wA.u.y, macA[ee]);
                macB[ee] = ffma2(g.u.x, wB.u.x, macB[ee]);
                macB[ee] = ffma2(g.u.y, wB.u.y, macB[ee]);
            }
        }

        // ---- node message scatter (scalar atomics: proven REDG fast path) ----
#pragma unroll
        for (int ee = 0; ee < EPB; ee++) {
            float a0, a1, b0, b1;
            upk2(macA[ee], a0, a1);
            upk2(macB[ee], b0, b1);
            float* oh = out + (size_t)dstn[ee] * 64;
            atomicAdd(&oh[2 * lane],     a0 + a1);
            atomicAdd(&oh[2 * lane + 1], b0 + b1);
        }
        __syncwarp();   // gbuf reuse safety across iterations
    }
}

// ---------------------------------------------------------------------------
extern "C" void kernel_launch(void* const* d_in, const int* in_sizes, int n_in,
                              void* d_out, int out_size) {
    const float* h    = (const float*)d_in[0];
    const float* x    = (const float*)d_in[1];
    const float* dist = (const float*)d_in[2];
    const float* We1  = (const float*)d_in[3];
    const float* be1  = (const float*)d_in[4];
    const float* We2  = (const float*)d_in[5];
    const float* be2  = (const float*)d_in[6];
    const float* Wn1  = (const float*)d_in[7];
    const float* bn1  = (const float*)d_in[8];
    const float* Wn2  = (const float*)d_in[9];
    const float* bn2  = (const float*)d_in[10];
    const float* Wc1  = (const float*)d_in[11];
    const float* bc1  = (const float*)d_in[12];
    const float* Wc2  = (const float*)d_in[13];
    const int*   eidx = (const int*)d_in[14];
    float* out = (float*)d_out;

    static bool attr_set = false;
    if (!attr_set) {
        cudaFuncSetAttribute(k_edge, cudaFuncAttributeMaxDynamicSharedMemorySize, 70 * 1024);
        attr_set = true;
    }

    k_fold<<<1, 128>>>(We2, be2, Wn1, bn1, Wc1, bc1, Wn2);
    k_tab<<<(NB + 1 + TB_BINS - 1) / TB_BINS, 256>>>(We1, be1);
    k_node<<<(N_NODES + NPB - 1) / NPB, 256>>>(h, Wn1, Wc1);
    k_init<<<2048, 256>>>(h, x, out);

    // smem: 8192 (WA,WB) + WPB*1024 (gbuf) + 192 small floats
    const int smem = (8192 + WPB * 1024 + 192) * sizeof(float);  // 66304 B
    k_edge<<<296, TPB, smem>>>(dist, eidx, x, bn2, Wc2, out);
}

// round 10
// speedup vs baseline: 1.1046x; 1.1046x over previous
#include <cuda_runtime.h>
#include <math.h>

#define N_NODES  50000
#define N_EDGES  800000
#define NODE_DIM 64
#define EDGE_DIM 32
#define HID      128
#define EPB      8
#define TPB      256
#define WPB      (TPB / 32)
#define NB       8192          // table bins over d in [0,15], nearest-neighbor
#define TB_BINS  8

typedef unsigned long long ull;

// Per-node precomputed rows [ns(128) | nd(128) | cs(128) | cd(128)]
__device__ float g_A[(size_t)N_NODES * 512];
// Folded edge-path weights (used only to build the table)
__device__ float g_Mn[32 * 128];
__device__ float g_Mc[32 * 128];
__device__ float g_bn[128];
__device__ float g_bc[128];
// Table: row i = [F(d_i)+bn (128) | G(d_i)+bc (128)], d_i = i*15/NB
__device__ float g_T[(size_t)(NB + 1) * 256];
// Rearranged Wn2: WA[i*32+l] = Wn2[4i..4i+3][2l], WB same for 2l+1
__device__ float4 g_WA[1024];
__device__ float4 g_WB[1024];

union F4 { float4 f; ulonglong2 u; };
union F2 { float2 f; ull u; };

__device__ __forceinline__ ull pk2(float x, float y) {
    ull r; asm("mov.b64 %0,{%1,%2};" : "=l"(r) : "f"(x), "f"(y)); return r;
}
__device__ __forceinline__ void upk2(ull v, float& x, float& y) {
    asm("mov.b64 {%0,%1},%2;" : "=f"(x), "=f"(y) : "l"(v));
}
__device__ __forceinline__ ull ffma2(ull a, ull b, ull c) {
    ull d; asm("fma.rn.f32x2 %0,%1,%2,%3;" : "=l"(d) : "l"(a), "l"(b), "l"(c)); return d;
}
__device__ __forceinline__ ull fadd2(ull a, ull b) {
    ull d; asm("add.rn.f32x2 %0,%1,%2;" : "=l"(d) : "l"(a), "l"(b)); return d;
}
// silu via MUFU tanh: silu(z) = hz + hz*tanh(hz), hz = z/2
__device__ __forceinline__ float silu1(float z) {
    float hz = 0.5f * z;
    float th;
    asm("tanh.approx.f32 %0, %1;" : "=f"(th) : "f"(hz));
    return fmaf(hz, th, hz);
}

// ---------------------------------------------------------------------------
// K0: fold edge-path weights + rearrange Wn2
// ---------------------------------------------------------------------------
__global__ void k_fold(const float* __restrict__ We2, const float* __restrict__ be2,
                       const float* __restrict__ Wn1, const float* __restrict__ bn1,
                       const float* __restrict__ Wc1, const float* __restrict__ bc1,
                       const float* __restrict__ Wn2) {
    int j = threadIdx.x;  // 0..127
    float bn = bn1[j], bc = bc1[j];
    for (int b = 0; b < 32; b++) {
        bn += be2[b] * Wn1[(128 + b) * 128 + j];
        bc += be2[b] * Wc1[(128 + b) * 128 + j];
    }
    g_bn[j] = bn;
    g_bc[j] = bc;
    for (int a = 0; a < 32; a++) {
        float sn = 0.f, sc = 0.f;
        for (int b = 0; b < 32; b++) {
            float w = We2[a * 32 + b];
            sn += w * Wn1[(128 + b) * 128 + j];
            sc += w * Wc1[(128 + b) * 128 + j];
        }
        g_Mn[a * 128 + j] = sn;
        g_Mc[a * 128 + j] = sc;
    }
    for (int idx = j; idx < 1024; idx += 128) {
        int i = idx >> 5, l = idx & 31;
        g_WA[idx] = make_float4(Wn2[(4 * i + 0) * 64 + 2 * l], Wn2[(4 * i + 1) * 64 + 2 * l],
                                Wn2[(4 * i + 2) * 64 + 2 * l], Wn2[(4 * i + 3) * 64 + 2 * l]);
        g_WB[idx] = make_float4(Wn2[(4 * i + 0) * 64 + 2 * l + 1], Wn2[(4 * i + 1) * 64 + 2 * l + 1],
                                Wn2[(4 * i + 2) * 64 + 2 * l + 1], Wn2[(4 * i + 3) * 64 + 2 * l + 1]);
    }
}

// ---------------------------------------------------------------------------
// K0b: build edge-path table. TB_BINS bins per block, smem-staged M.
// ---------------------------------------------------------------------------
__global__ void k_tab(const float* __restrict__ We1, const float* __restrict__ be1) {
    __shared__ float M_sh[8192];   // Mn(4096) | Mc(4096)
    __shared__ float b_sh[256];    // bn(128) | bc(128)
    __shared__ float t_sh[32];
    int j = threadIdx.x;           // 0..255
    for (int i = j; i < 4096; i += 256) {
        M_sh[i]        = g_Mn[i];
        M_sh[4096 + i] = g_Mc[i];
    }
    if (j < 128) {
        b_sh[j]       = g_bn[j];
        b_sh[128 + j] = g_bc[j];
    }
    __syncthreads();

    const float* M = (j < 128) ? M_sh : (M_sh + 4096);
    int jj = j & 127;
    float bb = b_sh[j];

    for (int bi = 0; bi < TB_BINS; bi++) {
        int i = blockIdx.x * TB_BINS + bi;
        if (i > NB) break;
        float d = (15.0f / NB) * i;
        if (j < 32) {
            float z = d * We1[j] + be1[j];
            t_sh[j] = z / (1.f + __expf(-z));   // exact silu for table accuracy
        }
        __syncthreads();
        float s = bb;
#pragma unroll 8
        for (int k = 0; k < 32; k++) s += t_sh[k] * M[k * 128 + jj];
        g_T[(size_t)i * 256 + j] = s;
        __syncthreads();
    }
}

// ---------------------------------------------------------------------------
// K1: per-node precompute, f32x2 math. 128 threads, NPB=16 (round-7 proven).
// ---------------------------------------------------------------------------
#define NPB 16
__global__ void k_node(const float* __restrict__ h,
                       const float* __restrict__ Wn1,
                       const float* __restrict__ Wc1) {
    __shared__ ull h2[NPB * 64];   // duplicated {h,h} pairs
    int node0 = blockIdx.x * NPB;
    for (int i = threadIdx.x; i < NPB * 64; i += 128) {
        float hv = h[node0 * 64 + i];
        h2[i] = pk2(hv, hv);
    }
    __syncthreads();
    int j = threadIdx.x;
    int m = j >> 5;
    int c = (j & 31) * 4;
    const float* W = ((m & 2) ? Wc1 : Wn1) + ((m & 1) ? 64 * 128 : 0);

    ull a0[NPB], a1[NPB];
#pragma unroll
    for (int n = 0; n < NPB; n++) { a0[n] = 0ull; a1[n] = 0ull; }
#pragma unroll 4
    for (int k = 0; k < 64; k++) {
        F4 w; w.f = *(const float4*)&W[k * 128 + c];
#pragma unroll
        for (int n = 0; n < NPB; n++) {
            ull hv = h2[n * 64 + k];
            a0[n] = ffma2(hv, w.u.x, a0[n]);
            a1[n] = ffma2(hv, w.u.y, a1[n]);
        }
    }
#pragma unroll
    for (int n = 0; n < NPB; n++) {
        F4 r; r.u.x = a0[n]; r.u.y = a1[n];
        *(float4*)&g_A[(size_t)(node0 + n) * 512 + m * 128 + c] = r.f;
    }
}

// ---------------------------------------------------------------------------
// K2: initialize output with (h, x), float4-vectorized
// ---------------------------------------------------------------------------
__global__ void k_init(const float4* __restrict__ h4, const float4* __restrict__ x4,
                       float4* __restrict__ out4) {
    const int nh4  = N_NODES * 16;          // 800000
    const int tot4 = nh4 + N_NODES * 3 / 4; // 837500
    for (int i = blockIdx.x * blockDim.x + threadIdx.x; i < tot4; i += gridDim.x * blockDim.x)
        out4[i] = (i < nh4) ? h4[i] : x4[i - nh4];
}

// ---------------------------------------------------------------------------
// K3: edge kernel. Nearest-neighbor table edge path; no k-loops, no spills.
// ---------------------------------------------------------------------------
__global__ void __launch_bounds__(TPB, 2)
k_edge(const float* __restrict__ dist,
       const int*   __restrict__ eidx,
       const float* __restrict__ x,
       const float* __restrict__ bn2,
       const float* __restrict__ Wc2,
       float* __restrict__ out) {
    extern __shared__ float sm[];
    float4* WA_sh = (float4*)sm;               // 1024 f4
    float4* WB_sh = WA_sh + 1024;              // 1024 f4
    float*  gbuf  = (float*)(WB_sh + 1024);    // WPB warps * 1024
    float*  Wc2_sh = gbuf + WPB * 1024;        // 128
    float*  bn2_sh = Wc2_sh + 128;             // 64

    for (int i = threadIdx.x; i < 1024; i += blockDim.x) {
        WA_sh[i] = g_WA[i];
        WB_sh[i] = g_WB[i];
    }
    if (threadIdx.x < 128) Wc2_sh[threadIdx.x] = Wc2[threadIdx.x];
    if (threadIdx.x < 64)  bn2_sh[threadIdx.x] = bn2[threadIdx.x];
    __syncthreads();

    const int lane = threadIdx.x & 31;
    const int wib  = threadIdx.x >> 5;
    const int gw   = blockIdx.x * WPB + wib;
    const int nw   = gridDim.x * WPB;

    F4 wc2_4; wc2_4.f = *(const float4*)&Wc2_sh[4 * lane];
    const float2 bn2_2 = *(const float2*)&bn2_sh[2 * lane];
    float* gb = gbuf + wib * 1024;
    const float4* A4 = (const float4*)g_A;
    const float4* T4 = (const float4*)g_T;     // 64 f4 per table row
    const float4* gb4 = (const float4*)gb;
    float* out_x = out + (size_t)N_NODES * 64;

    for (int base = gw * EPB; base < N_EDGES; base += nw * EPB) {
        int src[EPB], dstn[EPB];
        float cw[EPB];

        // ---- per-edge: nearest-table edge path + node terms for both MLPs ----
#pragma unroll
        for (int ee = 0; ee < EPB; ee++) {
            int e = base + ee;
            float d = dist[e];
            int s  = eidx[e];
            int dd = eidx[N_EDGES + e];
            src[ee] = s; dstn[ee] = dd;

            float p = d * (NB / 15.0f) + 0.5f;
            int i0 = (int)p;
            i0 = max(0, min(i0, NB));
            const float4* t0 = T4 + (size_t)i0 * 64;

            // node-MLP hidden: pn = A_ns[src] + A_nd[dst] + F(d)
            {
                F4 a;  a.f  = A4[(size_t)s  * 128 + lane];
                F4 b;  b.f  = A4[(size_t)dd * 128 + 32 + lane];
                F4 f0; f0.f = t0[lane];
                ull px = fadd2(fadd2(a.u.x, b.u.x), f0.u.x);
                ull py = fadd2(fadd2(a.u.y, b.u.y), f0.u.y);
                float p0, p1, p2, p3;
                upk2(px, p0, p1);
                upk2(py, p2, p3);
                float4 gn = make_float4(silu1(p0), silu1(p1), silu1(p2), silu1(p3));
                *(float4*)&gb[ee * 128 + 4 * lane] = gn;
            }
            // coord-MLP hidden -> scalar cw
            {
                F4 c;  c.f  = A4[(size_t)s  * 128 + 64 + lane];
                F4 dv; dv.f = A4[(size_t)dd * 128 + 96 + lane];
                F4 g0; g0.f = t0[32 + lane];
                ull px = fadd2(fadd2(c.u.x, dv.u.x), g0.u.x);
                ull py = fadd2(fadd2(c.u.y, dv.u.y), g0.u.y);
                float p0, p1, p2, p3;
                upk2(px, p0, p1);
                upk2(py, p2, p3);
                float ss = silu1(p0) * wc2_4.f.x + silu1(p1) * wc2_4.f.y
                         + silu1(p2) * wc2_4.f.z + silu1(p3) * wc2_4.f.w;
#pragma unroll
                for (int off = 16; off > 0; off >>= 1)
                    ss += __shfl_xor_sync(0xffffffffu, ss, off);
                cw[ee] = ss;
            }
        }

        // ---- coord scatter (lanes 0..7, one edge each) ----
        if (lane < EPB) {
            float mycw = cw[0]; int ms = src[0], md = dstn[0];
#pragma unroll
            for (int ee = 1; ee < EPB; ee++)
                if (lane == ee) { mycw = cw[ee]; ms = src[ee]; md = dstn[ee]; }
            float dx = x[ms * 3 + 0] - x[md * 3 + 0];
            float dy = x[ms * 3 + 1] - x[md * 3 + 1];
            float dz = x[ms * 3 + 2] - x[md * 3 + 2];
            float len = fmaxf(sqrtf(dx * dx + dy * dy + dz * dz), 1e-8f);
            float inv = mycw / len;
            float* ox = out_x + (size_t)md * 3;
            atomicAdd(&ox[0], dx * inv);
            atomicAdd(&ox[1], dy * inv);
            atomicAdd(&ox[2], dz * inv);
        }
        __syncwarp();

        // ---- phase 2: gn(128) @ Wn2 -> 64 ----
        ull macA[EPB], macB[EPB];
#pragma unroll
        for (int ee = 0; ee < EPB; ee++) {
            macA[ee] = pk2(bn2_2.x, 0.f);
            macB[ee] = pk2(bn2_2.y, 0.f);
        }
#pragma unroll
        for (int i = 0; i < 32; i++) {
            F4 wA; wA.f = WA_sh[i * 32 + lane];
            F4 wB; wB.f = WB_sh[i * 32 + lane];
#pragma unroll
            for (int ee = 0; ee < EPB; ee++) {
                F4 g; g.f = gb4[ee * 32 + i];  // broadcast
                macA[ee] = ffma2(g.u.x, wA.u.x, macA[ee]);
                macA[ee] = ffma2(g.u.y, wA.u.y, macA[ee]);
                macB[ee] = ffma2(g.u.x, wB.u.x, macB[ee]);
                macB[ee] = ffma2(g.u.y, wB.u.y, macB[ee]);
            }
        }

        // ---- node message scatter (scalar atomics: proven REDG fast path) ----
#pragma unroll
        for (int ee = 0; ee < EPB; ee++) {
            float a0, a1, b0, b1;
            upk2(macA[ee], a0, a1);
            upk2(macB[ee], b0, b1);
            float* oh = out + (size_t)dstn[ee] * 64;
            atomicAdd(&oh[2 * lane],     a0 + a1);
            atomicAdd(&oh[2 * lane + 1], b0 + b1);
        }
        __syncwarp();   // gbuf reuse safety across iterations
    }
}

// ---------------------------------------------------------------------------
extern "C" void kernel_launch(void* const* d_in, const int* in_sizes, int n_in,
                              void* d_out, int out_size) {
    const float* h    = (const float*)d_in[0];
    const float* x    = (const float*)d_in[1];
    const float* dist = (const float*)d_in[2];
    const float* We1  = (const float*)d_in[3];
    const float* be1  = (const float*)d_in[4];
    const float* We2  = (const float*)d_in[5];
    const float* be2  = (const float*)d_in[6];
    const float* Wn1  = (const float*)d_in[7];
    const float* bn1  = (const float*)d_in[8];
    const float* Wn2  = (const float*)d_in[9];
    const float* bn2  = (const float*)d_in[10];
    const float* Wc1  = (const float*)d_in[11];
    const float* bc1  = (const float*)d_in[12];
    const float* Wc2  = (const float*)d_in[13];
    const int*   eidx = (const int*)d_in[14];
    float* out = (float*)d_out;

    static bool attr_set = false;
    if (!attr_set) {
        cudaFuncSetAttribute(k_edge, cudaFuncAttributeMaxDynamicSharedMemorySize, 70 * 1024);
        attr_set = true;
    }

    k_fold<<<1, 128>>>(We2, be2, Wn1, bn1, Wc1, bc1, Wn2);
    k_tab<<<(NB + 1 + TB_BINS - 1) / TB_BINS, 256>>>(We1, be1);
    k_node<<<N_NODES / NPB, 128>>>(h, Wn1, Wc1);
    k_init<<<1024, 256>>>((const float4*)h, (const float4*)x, (float4*)out);

    // smem: 8192 (WA,WB) + WPB*1024 (gbuf) + 192 small floats
    const int smem = (8192 + WPB * 1024 + 192) * sizeof(float);  // 66304 B
    k_edge<<<296, TPB, smem>>>(dist, eidx, x, bn2, Wc2, out);
}